// round 4
// baseline (speedup 1.0000x reference)
#include <cuda_runtime.h>
#include <math.h>

#define NF     256
#define TOPK   32
#define WIN    128
#define EMB    128
#define BATCH  64
#define ALPHA  0.2f

// Scratch: Wx = x @ W + b, shape [BATCH*NF, EMB] = 8 MB (device global, no alloc)
__device__ float g_wx[BATCH * NF * EMB];

// ---------------------------------------------------------------------------
// Kernel 1: Wx[r][e] = sum_w x[r][w] * W[w][e] + b[e]
// M=16384, N=128, K=128. BM=64, BN=128, BK=16; 256 threads; 4x8 micro-tile.
// ---------------------------------------------------------------------------
__global__ __launch_bounds__(256) void gemm_kernel(const float* __restrict__ x,
                                                   const float* __restrict__ W,
                                                   const float* __restrict__ bias) {
    __shared__ float As[64][17];    // padded to dodge bank conflicts on scalar reads
    __shared__ float Bs[16][128];

    const int tid  = threadIdx.x;
    const int row0 = blockIdx.x * 64;
    const int ty   = tid >> 4;      // 0..15 -> rows ty*4..ty*4+3
    const int tx   = tid & 15;      // 0..15 -> cols tx*8..tx*8+7

    float acc[4][8];
#pragma unroll
    for (int i = 0; i < 4; i++)
#pragma unroll
        for (int j = 0; j < 8; j++) acc[i][j] = 0.f;

    const int ar = tid >> 2;          // 0..63
    const int ak = (tid & 3) << 2;    // 0,4,8,12

    for (int kc = 0; kc < 128; kc += 16) {
        // A tile: 64x16
        float4 av = *(const float4*)(x + (size_t)(row0 + ar) * 128 + kc + ak);
        As[ar][ak + 0] = av.x; As[ar][ak + 1] = av.y;
        As[ar][ak + 2] = av.z; As[ar][ak + 3] = av.w;
        // B tile: 16x128 = 512 float4, 2 per thread
#pragma unroll
        for (int i = 0; i < 2; i++) {
            int idx = tid + i * 256;
            int kr  = idx >> 5;
            int cc  = (idx & 31) << 2;
            *(float4*)(&Bs[kr][cc]) =
                *(const float4*)(W + (size_t)(kc + kr) * 128 + cc);
        }
        __syncthreads();
#pragma unroll
        for (int k = 0; k < 16; k++) {
            float a[4];
#pragma unroll
            for (int i = 0; i < 4; i++) a[i] = As[ty * 4 + i][k];
            float4 b0 = *(float4*)(&Bs[k][tx * 8]);
            float4 b1 = *(float4*)(&Bs[k][tx * 8 + 4]);
            float bb[8] = {b0.x, b0.y, b0.z, b0.w, b1.x, b1.y, b1.z, b1.w};
#pragma unroll
            for (int i = 0; i < 4; i++)
#pragma unroll
                for (int j = 0; j < 8; j++)
                    acc[i][j] = fmaf(a[i], bb[j], acc[i][j]);
        }
        __syncthreads();
    }

#pragma unroll
    for (int i = 0; i < 4; i++) {
        int row = row0 + ty * 4 + i;
#pragma unroll
        for (int j = 0; j < 8; j += 4) {
            float4 v;
            v.x = acc[i][j + 0] + bias[tx * 8 + j + 0];
            v.y = acc[i][j + 1] + bias[tx * 8 + j + 1];
            v.z = acc[i][j + 2] + bias[tx * 8 + j + 2];
            v.w = acc[i][j + 3] + bias[tx * 8 + j + 3];
            *(float4*)(g_wx + (size_t)row * 128 + tx * 8 + j) = v;
        }
    }
}

// ---------------------------------------------------------------------------
// Kernel 2: one CTA per (b, n).
//  - gather 32 neighbor rows + self row of Wx into SMEM (float4)
//  - p_j = dot(row_j, a1), q_j = dot(row_j, a2)
//  - e[k<16] = lrelu(p_self + q_self); e[k>=16] = lrelu(p[2(k-16)] + q[2(k-16)+1])
//    (from concat-axis2 + reshape analysis), + nan_to_num(bias_n)
//  - softmax over 32 k, then stream out lrelu(att[k] * row_k)
// ---------------------------------------------------------------------------
__global__ __launch_bounds__(256) void attn_kernel(const int*   __restrict__ edges,
                                                   const float* __restrict__ avec,
                                                   const float* __restrict__ bias_n,
                                                   float*       __restrict__ out) {
    __shared__ float sh[33][128];   // 0..31 = neighbor rows, 32 = self row
    __shared__ float sa[256];       // a[:,0]
    __shared__ int   snbr[32];
    __shared__ float sp[33], sq[33];
    __shared__ float satt[32];

    const int bn  = blockIdx.x;
    const int b   = bn >> 8;
    const int n   = bn & 255;
    const int tid = threadIdx.x;

    if (tid < 32) snbr[tid] = edges[n * 32 + tid];   // edge_indices[0] row
    sa[tid] = avec[tid];                             // 256 threads, 256 elems
    __syncthreads();

    // Gather 33 rows * 32 float4 (g_wx is L2-resident: 8 MB total)
    for (int idx = tid; idx < 33 * 32; idx += 256) {
        int r  = idx >> 5;
        int c4 = (idx & 31) << 2;
        int grow = (r < 32) ? (b * NF + snbr[r]) : bn;
        *(float4*)(&sh[r][c4]) =
            *(const float4*)(g_wx + (size_t)grow * 128 + c4);
    }
    __syncthreads();

    // Per-row dot products with a1 (sa[0:128]) and a2 (sa[128:256])
    const int wid = tid >> 5, lane = tid & 31;
    for (int j = wid; j < 33; j += 8) {
        float p = 0.f, q = 0.f;
#pragma unroll
        for (int c = 0; c < 4; c++) {
            float v = sh[j][lane + 32 * c];
            p = fmaf(v, sa[lane + 32 * c], p);
            q = fmaf(v, sa[128 + lane + 32 * c], q);
        }
#pragma unroll
        for (int o = 16; o; o >>= 1) {
            p += __shfl_down_sync(0xffffffffu, p, o);
            q += __shfl_down_sync(0xffffffffu, q, o);
        }
        if (lane == 0) { sp[j] = p; sq[j] = q; }
    }
    __syncthreads();

    // Softmax over the 32 attention logits (warp 0)
    if (tid < 32) {
        int k = tid;
        float raw = (k < 16) ? (sp[32] + sq[32])
                             : (sp[2 * (k - 16)] + sq[2 * (k - 16) + 1]);
        float e = raw > 0.f ? raw : ALPHA * raw;
        float bz = bias_n[n * 32 + k];
        if (isnan(bz))       bz = 0.f;
        else if (isinf(bz))  bz = bz > 0.f ? 3.402823466e38f : -3.402823466e38f;
        e += bz;
        float mx = e;
#pragma unroll
        for (int o = 16; o; o >>= 1) mx = fmaxf(mx, __shfl_xor_sync(0xffffffffu, mx, o));
        float ex = __expf(e - mx);   // arg <= 0, moderate range: fast exp is safe
        float s = ex;
#pragma unroll
        for (int o = 16; o; o >>= 1) s += __shfl_xor_sync(0xffffffffu, s, o);
        satt[k] = ex / s;
    }
    __syncthreads();

    // Stream output: 32 k * 128 e = 1024 float4 per CTA, coalesced 16 KB
    float* outb = out + (size_t)bn * (TOPK * EMB);
    for (int idx = tid; idx < TOPK * 32; idx += 256) {
        int k  = idx >> 5;
        int c4 = (idx & 31) << 2;
        float att = satt[k];
        float4 v = *(float4*)(&sh[k][c4]);
        v.x *= att; v.y *= att; v.z *= att; v.w *= att;
        v.x = v.x > 0.f ? v.x : ALPHA * v.x;
        v.y = v.y > 0.f ? v.y : ALPHA * v.y;
        v.z = v.z > 0.f ? v.z : ALPHA * v.z;
        v.w = v.w > 0.f ? v.w : ALPHA * v.w;
        *(float4*)(outb + k * 128 + c4) = v;
    }
}

// ---------------------------------------------------------------------------
// Inputs (metadata order): x_n, x_e(unused), edge_indices, all_embeddings(unused),
//                          W_n, b_n, a, bias_n. Output: float32 [B,NF,K,E].
// ---------------------------------------------------------------------------
extern "C" void kernel_launch(void* const* d_in, const int* in_sizes, int n_in,
                              void* d_out, int out_size) {
    const float* x      = (const float*)d_in[0];
    const int*   edges  = (const int*)  d_in[2];
    const float* W      = (const float*)d_in[4];
    const float* bvec   = (const float*)d_in[5];
    const float* a      = (const float*)d_in[6];
    const float* biasn  = (const float*)d_in[7];
    float*       out    = (float*)d_out;

    gemm_kernel<<<(BATCH * NF) / 64, 256>>>(x, W, bvec);
    attn_kernel<<<BATCH * NF, 256>>>(edges, a, biasn, out);
}

// round 6
// speedup vs baseline: 1.1494x; 1.1494x over previous
#include <cuda_runtime.h>
#include <math.h>

#define NF     256
#define TOPK   32
#define WIN    128
#define EMB    128
#define BATCH  64
#define ALPHA  0.2f

// Scratch: Wx = x @ W + b, shape [BATCH*NF, EMB] = 8 MB (device global, no alloc)
__device__ float g_wx[BATCH * NF * EMB];

// ---------------------------------------------------------------------------
// Kernel 1: Wx[r][e] = sum_w x[r][w] * W[w][e] + b[e]
// M=16384, N=128, K=128. BM=64; W (128x128, 64KB) fully SMEM-resident;
// A tiles (64x16) double-buffered -> ONE __syncthreads per K-step.
// 256 threads; 4x8 micro-tile per thread.
// ---------------------------------------------------------------------------
__global__ __launch_bounds__(256) void gemm_kernel(const float* __restrict__ x,
                                                   const float* __restrict__ W,
                                                   const float* __restrict__ bias) {
    __shared__ float Ws[128][128];     // full W, 64 KB
    __shared__ float As[2][64][17];    // double-buffered A tile, padded

    const int tid  = threadIdx.x;
    const int row0 = blockIdx.x * 64;
    const int ty   = tid >> 4;         // 0..15 -> rows ty*4..ty*4+3
    const int tx   = tid & 15;         // 0..15 -> cols tx*8..tx*8+7

    // Load full W: 4096 float4, 16 per thread (coalesced)
#pragma unroll
    for (int i = 0; i < 16; i++) {
        int idx = tid + i * 256;
        int kr  = idx >> 5;
        int cc  = (idx & 31) << 2;
        *(float4*)(&Ws[kr][cc]) = *(const float4*)(W + (size_t)kr * 128 + cc);
    }

    // A loader mapping: thread -> (row ar, k-chunk ak)
    const int ar = tid >> 2;           // 0..63
    const int ak = (tid & 3) << 2;     // 0,4,8,12
    const float* xrow = x + (size_t)(row0 + ar) * 128 + ak;

    // Preload first A tile into buffer 0
    {
        float4 av = *(const float4*)(xrow);
        As[0][ar][ak + 0] = av.x; As[0][ar][ak + 1] = av.y;
        As[0][ar][ak + 2] = av.z; As[0][ar][ak + 3] = av.w;
    }
    __syncthreads();

    float acc[4][8];
#pragma unroll
    for (int i = 0; i < 4; i++)
#pragma unroll
        for (int j = 0; j < 8; j++) acc[i][j] = 0.f;

#pragma unroll
    for (int kc = 0; kc < 8; kc++) {
        const int cur = kc & 1;
        float4 nxt;
        if (kc < 7) nxt = *(const float4*)(xrow + (kc + 1) * 16);

#pragma unroll
        for (int k = 0; k < 16; k++) {
            float a[4];
#pragma unroll
            for (int i = 0; i < 4; i++) a[i] = As[cur][ty * 4 + i][k];
            float4 b0 = *(float4*)(&Ws[kc * 16 + k][tx * 8]);
            float4 b1 = *(float4*)(&Ws[kc * 16 + k][tx * 8 + 4]);
            float bb[8] = {b0.x, b0.y, b0.z, b0.w, b1.x, b1.y, b1.z, b1.w};
#pragma unroll
            for (int i = 0; i < 4; i++)
#pragma unroll
                for (int j = 0; j < 8; j++)
                    acc[i][j] = fmaf(a[i], bb[j], acc[i][j]);
        }

        if (kc < 7) {
            // All warps are inside iteration kc (past the previous barrier),
            // reading buffer `cur`; writing `cur^1` is race-free.
            As[cur ^ 1][ar][ak + 0] = nxt.x; As[cur ^ 1][ar][ak + 1] = nxt.y;
            As[cur ^ 1][ar][ak + 2] = nxt.z; As[cur ^ 1][ar][ak + 3] = nxt.w;
            __syncthreads();
        }
    }

#pragma unroll
    for (int i = 0; i < 4; i++) {
        int row = row0 + ty * 4 + i;
#pragma unroll
        for (int j = 0; j < 8; j += 4) {
            float4 v;
            v.x = acc[i][j + 0] + bias[tx * 8 + j + 0];
            v.y = acc[i][j + 1] + bias[tx * 8 + j + 1];
            v.z = acc[i][j + 2] + bias[tx * 8 + j + 2];
            v.w = acc[i][j + 3] + bias[tx * 8 + j + 3];
            *(float4*)(g_wx + (size_t)row * 128 + tx * 8 + j) = v;
        }
    }
}

// ---------------------------------------------------------------------------
// Kernel 2: one CTA per (b, n). Register-resident rows (no SMEM tile!):
// a warp's 32 lanes cover one 128-float row as float4s. Warp w owns output
// rows {w, w+8, w+16, w+24}; warp 0 also computes the self row (logits only).
//  - p_j = dot(row_j, a1), q_j = dot(row_j, a2) via inline FMA + warp reduce
//  - e[k<16] = lrelu(p_self + q_self); e[k>=16] = lrelu(p[2(k-16)] + q[2(k-16)+1])
//    + nan_to_num(bias_n); softmax over k; out = lrelu(att[k] * row_k)
// Only sp/sq/satt (132 B) touch SMEM; output streamed with __stcs.
// ---------------------------------------------------------------------------
__global__ __launch_bounds__(256) void attn_kernel(const int*   __restrict__ edges,
                                                   const float* __restrict__ avec,
                                                   const float* __restrict__ bias_n,
                                                   float*       __restrict__ out) {
    __shared__ float sp[33], sq[33];
    __shared__ float satt[32];

    const int bn   = blockIdx.x;
    const int b    = bn >> 8;
    const int n    = bn & 255;
    const int tid  = threadIdx.x;
    const int wid  = tid >> 5;
    const int lane = tid & 31;

    // a[:,0] held in registers: a1 = a[0:128], a2 = a[128:256]
    const float4 a1 = *(const float4*)(avec + lane * 4);
    const float4 a2 = *(const float4*)(avec + 128 + lane * 4);

    float4 vrow[4];

#pragma unroll
    for (int i = 0; i < 4; i++) {
        const int j  = wid + i * 8;                       // row 0..31
        const int nb = __ldg(edges + n * 32 + j);         // uniform across warp
        const float4 v = *(const float4*)(g_wx + (size_t)(b * NF + nb) * 128 + lane * 4);
        vrow[i] = v;
        float p = v.x * a1.x + v.y * a1.y + v.z * a1.z + v.w * a1.w;
        float q = v.x * a2.x + v.y * a2.y + v.z * a2.z + v.w * a2.w;
#pragma unroll
        for (int o = 16; o; o >>= 1) {
            p += __shfl_down_sync(0xffffffffu, p, o);
            q += __shfl_down_sync(0xffffffffu, q, o);
        }
        if (lane == 0) { sp[j] = p; sq[j] = q; }
    }

    if (wid == 0) {  // self row: logits only
        const float4 v = *(const float4*)(g_wx + (size_t)bn * 128 + lane * 4);
        float p = v.x * a1.x + v.y * a1.y + v.z * a1.z + v.w * a1.w;
        float q = v.x * a2.x + v.y * a2.y + v.z * a2.z + v.w * a2.w;
#pragma unroll
        for (int o = 16; o; o >>= 1) {
            p += __shfl_down_sync(0xffffffffu, p, o);
            q += __shfl_down_sync(0xffffffffu, q, o);
        }
        if (lane == 0) { sp[32] = p; sq[32] = q; }
    }
    __syncthreads();

    // Softmax over the 32 attention logits (warp 0)
    if (tid < 32) {
        int k = tid;
        float raw = (k < 16) ? (sp[32] + sq[32])
                             : (sp[2 * (k - 16)] + sq[2 * (k - 16) + 1]);
        float e = raw > 0.f ? raw : ALPHA * raw;
        float bz = bias_n[n * 32 + k];
        if (isnan(bz))       bz = 0.f;
        else if (isinf(bz))  bz = bz > 0.f ? 3.402823466e38f : -3.402823466e38f;
        e += bz;
        float mx = e;
#pragma unroll
        for (int o = 16; o; o >>= 1) mx = fmaxf(mx, __shfl_xor_sync(0xffffffffu, mx, o));
        float ex = __expf(e - mx);   // arg <= 0, moderate range
        float s = ex;
#pragma unroll
        for (int o = 16; o; o >>= 1) s += __shfl_xor_sync(0xffffffffu, s, o);
        satt[k] = ex / s;
    }
    __syncthreads();

    // Output from registers: warp w writes its 4 rows, 512B coalesced each.
    float* outb = out + (size_t)bn * (TOPK * EMB);
#pragma unroll
    for (int i = 0; i < 4; i++) {
        const int j = wid + i * 8;
        const float att = satt[j];
        float4 v = vrow[i];
        v.x *= att; v.y *= att; v.z *= att; v.w *= att;
        v.x = v.x > 0.f ? v.x : ALPHA * v.x;
        v.y = v.y > 0.f ? v.y : ALPHA * v.y;
        v.z = v.z > 0.f ? v.z : ALPHA * v.z;
        v.w = v.w > 0.f ? v.w : ALPHA * v.w;
        __stcs((float4*)(outb + j * 128 + lane * 4), v);  // streaming: no L1 alloc
    }
}

// ---------------------------------------------------------------------------
// Inputs (metadata order): x_n, x_e(unused), edge_indices, all_embeddings(unused),
//                          W_n, b_n, a, bias_n. Output: float32 [B,NF,K,E].
// ---------------------------------------------------------------------------
extern "C" void kernel_launch(void* const* d_in, const int* in_sizes, int n_in,
                              void* d_out, int out_size) {
    const float* x      = (const float*)d_in[0];
    const int*   edges  = (const int*)  d_in[2];
    const float* W      = (const float*)d_in[4];
    const float* bvec   = (const float*)d_in[5];
    const float* a      = (const float*)d_in[6];
    const float* biasn  = (const float*)d_in[7];
    float*       out    = (float*)d_out;

    gemm_kernel<<<(BATCH * NF) / 64, 256>>>(x, W, bvec);
    attn_kernel<<<BATCH * NF, 256>>>(edges, a, biasn, out);
}